// round 1
// baseline (speedup 1.0000x reference)
#include <cuda_runtime.h>
#include <mma.h>
#include <cmath>

using namespace nvcuda;

#define BATCH 16
#define SEQL  512
#define DIMC  2048
#define NHEAD 16
#define HDIM  128
#define NQKV  6144
#define MTOT  (BATCH*SEQL)   // 8192

// Scratch (device globals: allocation-guard safe)
__device__ float g_q[(size_t)BATCH*NHEAD*SEQL*HDIM];  // [B,H,T,hd]
__device__ float g_k[(size_t)BATCH*NHEAD*SEQL*HDIM];
__device__ float g_v[(size_t)BATCH*NHEAD*SEQL*HDIM];
__device__ float g_y[(size_t)MTOT*DIMC];              // attention out, [B*T, C]

// ---------------------------------------------------------------------------
// TF32 GEMM: C[M,N] = A[M,2048] * B[2048,N]
// MODE 0: A = x, N=6144, epilogue scatters q/k/v into [B,H,T,hd] layout
// MODE 1: A = g_y, N=2048, epilogue writes Cout row-major
// ---------------------------------------------------------------------------
#define BM 128
#define BN 128
#define BK 32
#define APAD 4
#define BPAD 4

template<int MODE>
__global__ void __launch_bounds__(256)
gemm_tf32_kernel(const float* __restrict__ A, const float* __restrict__ B,
                 float* __restrict__ Cout, int N)
{
    __shared__ float As[BM][BK + APAD];
    __shared__ float Bs[BK][BN + BPAD];

    const int tid  = threadIdx.x;
    const int warp = tid >> 5;
    const int wm   = warp >> 1;      // 0..3  (rows of 32)
    const int wn   = warp & 1;       // 0..1  (cols of 64)
    const int tileM = blockIdx.y * BM;
    const int tileN = blockIdx.x * BN;

    const float* Aptr = (MODE == 1) ? g_y : A;

    wmma::fragment<wmma::accumulator, 16, 16, 8, float> acc[2][4];
#pragma unroll
    for (int i = 0; i < 2; i++)
#pragma unroll
        for (int j = 0; j < 4; j++) wmma::fill_fragment(acc[i][j], 0.0f);

    for (int k0 = 0; k0 < DIMC; k0 += BK) {
        // A tile: 128 x 32 (1024 float4, 4 per thread)
#pragma unroll
        for (int it = 0; it < 4; it++) {
            int idx = tid + it * 256;
            int row = idx >> 3;
            int c4  = idx & 7;
            float4 v = *(const float4*)(Aptr + (size_t)(tileM + row) * DIMC + k0 + c4 * 4);
            float* dst = &As[row][c4 * 4];
            dst[0] = wmma::__float_to_tf32(v.x);
            dst[1] = wmma::__float_to_tf32(v.y);
            dst[2] = wmma::__float_to_tf32(v.z);
            dst[3] = wmma::__float_to_tf32(v.w);
        }
        // B tile: 32 x 128
#pragma unroll
        for (int it = 0; it < 4; it++) {
            int idx = tid + it * 256;
            int row = idx >> 5;
            int c4  = idx & 31;
            float4 v = *(const float4*)(B + (size_t)(k0 + row) * N + tileN + c4 * 4);
            float* dst = &Bs[row][c4 * 4];
            dst[0] = wmma::__float_to_tf32(v.x);
            dst[1] = wmma::__float_to_tf32(v.y);
            dst[2] = wmma::__float_to_tf32(v.z);
            dst[3] = wmma::__float_to_tf32(v.w);
        }
        __syncthreads();

#pragma unroll
        for (int ks = 0; ks < 4; ks++) {
            wmma::fragment<wmma::matrix_a, 16, 16, 8, wmma::precision::tf32, wmma::row_major> af[2];
            wmma::fragment<wmma::matrix_b, 16, 16, 8, wmma::precision::tf32, wmma::row_major> bf[4];
#pragma unroll
            for (int i = 0; i < 2; i++)
                wmma::load_matrix_sync(af[i], &As[wm * 32 + i * 16][ks * 8], BK + APAD);
#pragma unroll
            for (int j = 0; j < 4; j++)
                wmma::load_matrix_sync(bf[j], &Bs[ks * 8][wn * 64 + j * 16], BN + BPAD);
#pragma unroll
            for (int i = 0; i < 2; i++)
#pragma unroll
                for (int j = 0; j < 4; j++)
                    wmma::mma_sync(acc[i][j], af[i], bf[j], acc[i][j]);
        }
        __syncthreads();
    }

    if (MODE == 1) {
#pragma unroll
        for (int i = 0; i < 2; i++)
#pragma unroll
            for (int j = 0; j < 4; j++) {
                float* cptr = Cout + (size_t)(tileM + wm * 32 + i * 16) * N
                                   + tileN + wn * 64 + j * 16;
                wmma::store_matrix_sync(cptr, acc[i][j], N, wmma::mem_row_major);
            }
    } else {
        // tileN spans exactly one (which, head): nb = tileN/128
        int nb    = blockIdx.x;
        int which = nb >> 4;     // 0:q 1:k 2:v
        int h     = nb & 15;
        int b     = tileM / SEQL;
        int t0    = tileM % SEQL;
        float* dstbase = (which == 0 ? g_q : (which == 1 ? g_k : g_v))
                       + (size_t)((b * NHEAD + h) * SEQL + t0) * HDIM;
#pragma unroll
        for (int i = 0; i < 2; i++)
#pragma unroll
            for (int j = 0; j < 4; j++) {
                float* cptr = dstbase + (size_t)(wm * 32 + i * 16) * HDIM + wn * 64 + j * 16;
                wmma::store_matrix_sync(cptr, acc[i][j], HDIM, wmma::mem_row_major);
            }
    }
}

// ---------------------------------------------------------------------------
// RoPE in-place on q and k: first 16 dims of each head, pairs (p, p+8)
// ---------------------------------------------------------------------------
__global__ void rope_kernel()
{
    int i = blockIdx.x * blockDim.x + threadIdx.x;
    const int per = BATCH * NHEAD * SEQL * 8;   // pairs per tensor
    if (i >= 2 * per) return;
    int which = i / per;
    int r  = i % per;
    int bh = r / (SEQL * 8);
    int t  = (r / 8) % SEQL;
    int p  = r & 7;

    float inv = powf(10000.0f, -(float)p / 8.0f);
    float ang = (float)t * inv;
    float c = cosf(ang), s = sinf(ang);

    float* base = (which ? g_k : g_q) + (size_t)(bh * SEQL + t) * HDIM;
    float x1 = base[p];
    float x2 = base[p + 8];
    base[p]     = x1 * c - x2 * s;
    base[p + 8] = x2 * c + x1 * s;
}

// ---------------------------------------------------------------------------
// Causal flash attention, fp32 SIMT. BQ=BK=64, 256 threads.
// Warp w owns q-rows [8w, 8w+8); lane l owns S cols {l, l+32} and dims [4l,4l+4).
// ---------------------------------------------------------------------------
#define AQ 64
#define AK 64
#define KTLD 65   // padded ld of transposed K

__global__ void __launch_bounds__(256)
attn_kernel(float* __restrict__ Y)
{
    extern __shared__ float sm[];
    float* Qs = sm;                        // 64*128
    float* Kt = Qs + AQ * HDIM;            // 128*65 (transposed K)
    float* Vs = Kt + HDIM * KTLD;          // 64*128
    float* Ps = Vs + AK * HDIM;            // 64*64

    const int tid = threadIdx.x;
    const int w   = tid >> 5;
    const int l   = tid & 31;
    const int bh  = blockIdx.y;            // 0..255
    const int qblk = blockIdx.x;           // 0..7
    const float scale = 0.08838834764831845f;   // 1/sqrt(128)

    const float* Qg = g_q + (size_t)bh * SEQL * HDIM;
    const float* Kg = g_k + (size_t)bh * SEQL * HDIM;
    const float* Vg = g_v + (size_t)bh * SEQL * HDIM;

    // Load Q block (scaled)
#pragma unroll
    for (int it = 0; it < 8; it++) {
        int idx = tid + it * 256;          // 0..2047 float4s
        int row = idx >> 5;
        int c4  = idx & 31;
        float4 v = *(const float4*)(Qg + (size_t)(qblk * AQ + row) * HDIM + c4 * 4);
        v.x *= scale; v.y *= scale; v.z *= scale; v.w *= scale;
        *(float4*)&Qs[row * HDIM + c4 * 4] = v;
    }

    float o[8][4];
    float mr[8], lr[8];
#pragma unroll
    for (int r = 0; r < 8; r++) {
        mr[r] = -INFINITY; lr[r] = 0.0f;
        o[r][0] = o[r][1] = o[r][2] = o[r][3] = 0.0f;
    }

    for (int j = 0; j <= qblk; j++) {
        __syncthreads();   // previous iter done with Kt/Vs
        // Load K (transposed) and V
#pragma unroll
        for (int it = 0; it < 8; it++) {
            int idx = tid + it * 256;
            int col = idx >> 5;
            int c4  = idx & 31;
            int kk  = c4 * 4;
            float4 kv = *(const float4*)(Kg + (size_t)(j * AK + col) * HDIM + kk);
            Kt[(kk + 0) * KTLD + col] = kv.x;
            Kt[(kk + 1) * KTLD + col] = kv.y;
            Kt[(kk + 2) * KTLD + col] = kv.z;
            Kt[(kk + 3) * KTLD + col] = kv.w;
            float4 vv = *(const float4*)(Vg + (size_t)(j * AK + col) * HDIM + kk);
            *(float4*)&Vs[col * HDIM + kk] = vv;
        }
        __syncthreads();

        // S = Q K^T (per thread: 8 rows x 2 cols)
        float s0[8], s1[8];
#pragma unroll
        for (int r = 0; r < 8; r++) { s0[r] = 0.0f; s1[r] = 0.0f; }
        for (int kk = 0; kk < HDIM; kk += 4) {
            float ka[4], kb[4];
#pragma unroll
            for (int u = 0; u < 4; u++) {
                ka[u] = Kt[(kk + u) * KTLD + l];
                kb[u] = Kt[(kk + u) * KTLD + l + 32];
            }
#pragma unroll
            for (int r = 0; r < 8; r++) {
                float4 qv = *(const float4*)&Qs[(w * 8 + r) * HDIM + kk];
                s0[r] += qv.x * ka[0] + qv.y * ka[1] + qv.z * ka[2] + qv.w * ka[3];
                s1[r] += qv.x * kb[0] + qv.y * kb[1] + qv.z * kb[2] + qv.w * kb[3];
            }
        }

        if (j == qblk) {
#pragma unroll
            for (int r = 0; r < 8; r++) {
                int row = w * 8 + r;
                if (l > row)      s0[r] = -1e30f;
                if (l + 32 > row) s1[r] = -1e30f;
            }
        }

        // Online softmax
#pragma unroll
        for (int r = 0; r < 8; r++) {
            float mx = fmaxf(s0[r], s1[r]);
#pragma unroll
            for (int off = 16; off; off >>= 1)
                mx = fmaxf(mx, __shfl_xor_sync(0xffffffffu, mx, off));
            float mnew  = fmaxf(mr[r], mx);
            float alpha = __expf(mr[r] - mnew);
            float p0 = __expf(s0[r] - mnew);
            float p1 = __expf(s1[r] - mnew);
            float rs = p0 + p1;
#pragma unroll
            for (int off = 16; off; off >>= 1)
                rs += __shfl_xor_sync(0xffffffffu, rs, off);
            lr[r] = lr[r] * alpha + rs;
            mr[r] = mnew;
            o[r][0] *= alpha; o[r][1] *= alpha; o[r][2] *= alpha; o[r][3] *= alpha;
            Ps[(w * 8 + r) * AK + l]      = p0;
            Ps[(w * 8 + r) * AK + l + 32] = p1;
        }
        __syncwarp();

        // O += P V
        for (int col = 0; col < AK; col++) {
            float4 vv = *(const float4*)&Vs[col * HDIM + 4 * l];
#pragma unroll
            for (int r = 0; r < 8; r++) {
                float p = Ps[(w * 8 + r) * AK + col];
                o[r][0] += p * vv.x;
                o[r][1] += p * vv.y;
                o[r][2] += p * vv.z;
                o[r][3] += p * vv.w;
            }
        }
    }

    // Write Y in [B*T, C] layout (head h at cols h*128..)
    int b = bh >> 4, h = bh & 15;
#pragma unroll
    for (int r = 0; r < 8; r++) {
        float inv = 1.0f / lr[r];
        int t = qblk * AQ + w * 8 + r;
        float4 ov;
        ov.x = o[r][0] * inv; ov.y = o[r][1] * inv;
        ov.z = o[r][2] * inv; ov.w = o[r][3] * inv;
        *(float4*)(Y + (size_t)(b * SEQL + t) * DIMC + h * HDIM + 4 * l) = ov;
    }
}

// ---------------------------------------------------------------------------
extern "C" void kernel_launch(void* const* d_in, const int* in_sizes, int n_in,
                              void* d_out, int out_size)
{
    const float* x    = (const float*)d_in[0];   // [16,512,2048]
    const float* Wqkv = (const float*)d_in[1];   // [2048,6144]
    const float* Wout = (const float*)d_in[2];   // [2048,2048]
    float* out = (float*)d_out;                  // [16,512,2048]

    // 1) QKV GEMM with fused scatter to [B,H,T,hd]
    gemm_tf32_kernel<0><<<dim3(NQKV / BN, MTOT / BM), 256>>>(x, Wqkv, nullptr, NQKV);

    // 2) RoPE on q,k (first 16 dims)
    {
        int total = 2 * BATCH * NHEAD * SEQL * 8;
        rope_kernel<<<(total + 255) / 256, 256>>>();
    }

    // 3) Causal flash attention
    {
        size_t smem = (size_t)(AQ * HDIM + HDIM * KTLD + AK * HDIM + AQ * AK) * sizeof(float);
        static bool attr_set = false;
        cudaFuncSetAttribute(attn_kernel, cudaFuncAttributeMaxDynamicSharedMemorySize, (int)smem);
        (void)attr_set;
        float* yp = nullptr;
        cudaGetSymbolAddress((void**)&yp, g_y);
        attn_kernel<<<dim3(SEQL / AQ, BATCH * NHEAD), 256, smem>>>(yp);
    }

    // 4) Output projection
    gemm_tf32_kernel<1><<<dim3(DIMC / BN, MTOT / BM), 256>>>(nullptr, Wout, out, DIMC);
}